// round 12
// baseline (speedup 1.0000x reference)
#include <cuda_runtime.h>
#include <cuda_bf16.h>
#include <cstdint>
#include <cstddef>

#define BB 2
#define TT 2048
#define CC 1024
#define HH 16
#define HD 64
#define MTOT (BB*TT)
#define DINLINE __device__ __forceinline__
typedef __nv_bfloat16 bf16;
typedef __nv_bfloat162 bf162;

// ---------------- scratch ---------------------------------------------------
__device__ bf16  g_hln_h [MTOT*CC],  g_hln_l [MTOT*CC];
__device__ float g_qkv   [MTOT*3*CC];
__device__ bf16  g_yatt_h[MTOT*CC],  g_yatt_l[MTOT*CC];
__device__ bf16  g_h2_h  [MTOT*CC],  g_h2_l  [MTOT*CC];
__device__ bf16  g_mact_h[(size_t)MTOT*4*CC], g_mact_l[(size_t)MTOT*4*CC];
__device__ bf16  g_wq_h [3*CC*CC], g_wq_l [3*CC*CC];
__device__ bf16  g_wap_h[CC*CC],   g_wap_l[CC*CC];
__device__ bf16  g_wfc_h[4*CC*CC], g_wfc_l[4*CC*CC];
__device__ bf16  g_wpr_h[CC*4*CC], g_wpr_l[CC*4*CC];
__device__ float g_entp[1024];

// ---------------- helpers ---------------------------------------------------
DINLINE uint32_t smem_u32(const void* p){ return (uint32_t)__cvta_generic_to_shared(p); }
DINLINE void cp16(uint32_t s, const void* g){
    asm volatile("cp.async.cg.shared.global [%0], [%1], 16;\n" :: "r"(s), "l"(g));
}
DINLINE void cp_commit(){ asm volatile("cp.async.commit_group;\n"); }

DINLINE uint32_t pack_bf16(float lo, float hi){
    bf162 t = __floats2bfloat162_rn(lo, hi);
    return *reinterpret_cast<uint32_t*>(&t);
}
DINLINE void split2(float x, bf16& h, bf16& l){
    h = __float2bfloat16_rn(x);
    l = __float2bfloat16_rn(x - __bfloat162float(h));
}
DINLINE void mma_bf16(float* d, uint32_t a0,uint32_t a1,uint32_t a2,uint32_t a3,
                      uint32_t b0, uint32_t b1){
    asm volatile("mma.sync.aligned.m16n8k16.row.col.f32.bf16.bf16.f32 "
        "{%0,%1,%2,%3},{%4,%5,%6,%7},{%8,%9},{%0,%1,%2,%3};\n"
        : "+f"(d[0]),"+f"(d[1]),"+f"(d[2]),"+f"(d[3])
        : "r"(a0),"r"(a1),"r"(a2),"r"(a3),"r"(b0),"r"(b1));
}
DINLINE void ldsm4(uint32_t* r, uint32_t addr){
    asm volatile("ldmatrix.sync.aligned.m8n8.x4.shared.b16 {%0,%1,%2,%3}, [%4];"
        : "=r"(r[0]), "=r"(r[1]), "=r"(r[2]), "=r"(r[3]) : "r"(addr));
}
DINLINE float gelu_tanh(float v){
    float u = 0.7978845608028654f * (v + 0.044715f * v * v * v);
    return 0.5f * v * (1.0f + tanhf(u));
}

// ---------------- weight split prep ----------------------------------------
__global__ void split_copy(const float* __restrict__ in, bf16* __restrict__ hi,
                           bf16* __restrict__ lo, int n4){
    int i = blockIdx.x * blockDim.x + threadIdx.x;
    int stride = gridDim.x * blockDim.x;
    for (; i < n4; i += stride){
        float4 v = ((const float4*)in)[i];
        bf16 h0,l0,h1,l1,h2,l2,h3,l3;
        split2(v.x,h0,l0); split2(v.y,h1,l1); split2(v.z,h2,l2); split2(v.w,h3,l3);
        ((bf162*)hi)[i*2  ] = bf162(h0,h1);
        ((bf162*)hi)[i*2+1] = bf162(h2,h3);
        ((bf162*)lo)[i*2  ] = bf162(l0,l1);
        ((bf162*)lo)[i*2+1] = bf162(l2,l3);
    }
}

// ---------------- LayerNorm -> hi/lo bf16 ----------------------------------
__global__ __launch_bounds__(256) void ln_kernel(
    const float* __restrict__ x, const float* __restrict__ w,
    const float* __restrict__ b, bf16* __restrict__ oh, bf16* __restrict__ ol)
{
    __shared__ float sS[8], sQ[8];
    __shared__ float sMean, sRstd;
    const int row = blockIdx.x, tid = threadIdx.x;
    float4 xv = *(const float4*)(x + (size_t)row * CC + tid * 4);
    float s = xv.x + xv.y + xv.z + xv.w;
    float q = xv.x*xv.x + xv.y*xv.y + xv.z*xv.z + xv.w*xv.w;
    #pragma unroll
    for (int o = 16; o; o >>= 1){
        s += __shfl_xor_sync(0xffffffffu, s, o);
        q += __shfl_xor_sync(0xffffffffu, q, o);
    }
    if ((tid & 31) == 0){ sS[tid >> 5] = s; sQ[tid >> 5] = q; }
    __syncthreads();
    if (tid == 0){
        float S = 0.f, Q = 0.f;
        #pragma unroll
        for (int i = 0; i < 8; i++){ S += sS[i]; Q += sQ[i]; }
        float mean = S * (1.0f / CC);
        sMean = mean; sRstd = rsqrtf(Q * (1.0f / CC) - mean * mean + 1e-5f);
    }
    __syncthreads();
    const float mean = sMean, r = sRstd;
    float4 wv = *(const float4*)(w + tid * 4);
    float4 bv = *(const float4*)(b + tid * 4);
    bf16 h0,l0,h1,l1,h2,l2,h3,l3;
    split2((xv.x - mean) * r * wv.x + bv.x, h0, l0);
    split2((xv.y - mean) * r * wv.y + bv.y, h1, l1);
    split2((xv.z - mean) * r * wv.z + bv.z, h2, l2);
    split2((xv.w - mean) * r * wv.w + bv.w, h3, l3);
    size_t o4 = (size_t)row * (CC/2) + tid * 2;
    ((bf162*)oh)[o4  ] = bf162(h0,h1);
    ((bf162*)oh)[o4+1] = bf162(h2,h3);
    ((bf162*)ol)[o4  ] = bf162(l0,l1);
    ((bf162*)ol)[o4+1] = bf162(l2,l3);
}

// ---------------- split-bf16 3-pass GEMM (mma.sync + ldmatrix) -------------
// out[M,N] = epi( (Ah+Al)[M,K] @ (Bh+Bl)[N,K]^T + bias[N] )
// 128x128 tile, BK=32, 8 warps (2m x 4n), double-buffered cp.async.
#define EPI_QKV  0
#define EPI_RES  1
#define EPI_GELU 2
#define ROWB   80u              // 32 bf16 data + 8 pad = 80 bytes/row
#define MATB   10240u           // 128 rows * 80B
#define STGB   40960u           // Ah|Al|Bh|Bl
#define GEMM_SMEM (2*STGB)      // 81920

template<int EPI>
__global__ __launch_bounds__(256) void gemm_mma(
    const bf16* __restrict__ Ah, const bf16* __restrict__ Al,
    const bf16* __restrict__ Bh, const bf16* __restrict__ Bl,
    const float* __restrict__ bias, const float* __restrict__ res,
    float* __restrict__ outf, bf16* __restrict__ outh, bf16* __restrict__ outl,
    int N, int K)
{
    extern __shared__ char dsm[];
    const uint32_t sb = smem_u32(dsm);
    const int tid = threadIdx.x, warp = tid >> 5, lane = tid & 31;
    const int bm = blockIdx.y * 128, bn = blockIdx.x * 128;
    const int wm = (warp >> 2) * 64, wn = (warp & 3) * 32;

    // cp.async mapping: thread -> row (tid>>1), two 16B chunks
    const int lrow = tid >> 1, lc = (tid & 1) * 2;
    const bf16* gA0 = Ah + (size_t)(bm + lrow) * K;
    const bf16* gA1 = Al + (size_t)(bm + lrow) * K;
    const bf16* gB0 = Bh + (size_t)(bn + lrow) * K;
    const bf16* gB1 = Bl + (size_t)(bn + lrow) * K;
    const uint32_t srow = (uint32_t)lrow * ROWB;

    // ldmatrix lane constants
    const int lr8 = (((lane >> 3) & 1) << 3) + (lane & 7);  // row offset within 16
    const int lk8 = (lane >> 4) << 3;                        // k offset (0 or 8)
    const int g = lane >> 2, tg = lane & 3;

    float acc[4][4][4];
    #pragma unroll
    for (int mi = 0; mi < 4; mi++)
        #pragma unroll
        for (int nf = 0; nf < 4; nf++){
            acc[mi][nf][0]=0.f; acc[mi][nf][1]=0.f; acc[mi][nf][2]=0.f; acc[mi][nf][3]=0.f;
        }

    const int KT = K >> 5;

    #define LOADST(J) do{ \
        const uint32_t _b = sb + (uint32_t)((J) & 1) * STGB; \
        const int _ko = (J) << 5; \
        _Pragma("unroll") \
        for (int c = 0; c < 2; c++){ \
            const uint32_t so = srow + (uint32_t)(lc + c) * 16u; \
            const int go = _ko + (lc + c) * 8; \
            cp16(_b            + so, gA0 + go); \
            cp16(_b +   MATB   + so, gA1 + go); \
            cp16(_b + 2u*MATB  + so, gB0 + go); \
            cp16(_b + 3u*MATB  + so, gB1 + go); \
        } \
        cp_commit(); \
    } while(0)

    LOADST(0);

    for (int kt = 0; kt < KT; ++kt){
        if (kt + 1 < KT){
            LOADST(kt + 1);
            asm volatile("cp.async.wait_group 1;\n");
        } else {
            asm volatile("cp.async.wait_group 0;\n");
        }
        __syncthreads();
        const uint32_t base = sb + (uint32_t)(kt & 1) * STGB;
        #pragma unroll
        for (int ks = 0; ks < 2; ++ks){
            const uint32_t kb = (uint32_t)((ks * 16 + lk8) * 2);
            uint32_t ah[4][4], al[4][4];
            #pragma unroll
            for (int mi = 0; mi < 4; mi++){
                const uint32_t ad = base + (uint32_t)(wm + mi*16 + lr8) * ROWB + kb;
                ldsm4(ah[mi], ad);
                ldsm4(al[mi], ad + MATB);
            }
            uint32_t bh[2][4], bl[2][4];
            #pragma unroll
            for (int ng = 0; ng < 2; ng++){
                const uint32_t bd = base + 2u*MATB + (uint32_t)(wn + ng*16 + lr8) * ROWB + kb;
                ldsm4(bh[ng], bd);
                ldsm4(bl[ng], bd + MATB);
            }
            #pragma unroll
            for (int mi = 0; mi < 4; mi++){
                #pragma unroll
                for (int nf = 0; nf < 4; nf++){
                    const int ng = nf >> 1, h = nf & 1;
                    const uint32_t b0h = bh[ng][h], b1h = bh[ng][2 + h];
                    const uint32_t b0l = bl[ng][h], b1l = bl[ng][2 + h];
                    mma_bf16(acc[mi][nf], ah[mi][0],ah[mi][1],ah[mi][2],ah[mi][3], b0h, b1h);
                    mma_bf16(acc[mi][nf], al[mi][0],al[mi][1],al[mi][2],al[mi][3], b0h, b1h);
                    mma_bf16(acc[mi][nf], ah[mi][0],ah[mi][1],ah[mi][2],ah[mi][3], b0l, b1l);
                }
            }
        }
        __syncthreads();
    }

    // epilogue
    #pragma unroll
    for (int mi = 0; mi < 4; mi++){
        const int m0 = bm + wm + mi * 16 + g;
        #pragma unroll
        for (int nf = 0; nf < 4; nf++){
            const int col = bn + wn + nf * 8 + tg * 2;
            const float bv0 = bias[col], bv1 = bias[col + 1];
            float v00 = acc[mi][nf][0] + bv0, v01 = acc[mi][nf][1] + bv1;
            float v10 = acc[mi][nf][2] + bv0, v11 = acc[mi][nf][3] + bv1;
            const size_t i0 = (size_t)m0 * N + col;
            const size_t i1 = (size_t)(m0 + 8) * N + col;
            if (EPI == EPI_RES){
                float2 r0v = *(const float2*)(res + i0);
                float2 r1v = *(const float2*)(res + i1);
                v00 += r0v.x; v01 += r0v.y; v10 += r1v.x; v11 += r1v.y;
                *(float2*)(outf + i0) = make_float2(v00, v01);
                *(float2*)(outf + i1) = make_float2(v10, v11);
            } else if (EPI == EPI_GELU){
                bf16 h0,l0,h1,l1;
                float g00 = gelu_tanh(v00), g01 = gelu_tanh(v01);
                float g10 = gelu_tanh(v10), g11 = gelu_tanh(v11);
                split2(g00, h0, l0); split2(g01, h1, l1);
                *(bf162*)(outh + i0) = bf162(h0, h1);
                *(bf162*)(outl + i0) = bf162(l0, l1);
                split2(g10, h0, l0); split2(g11, h1, l1);
                *(bf162*)(outh + i1) = bf162(h0, h1);
                *(bf162*)(outl + i1) = bf162(l0, l1);
            } else {
                *(float2*)(outf + i0) = make_float2(v00, v01);
                *(float2*)(outf + i1) = make_float2(v10, v11);
            }
        }
    }
    #undef LOADST
}

// ---------------- flash attention + streaming entropy ----------------------
__global__ __launch_bounds__(128) void flash_kernel(
    const float* __restrict__ qkv, bf16* __restrict__ yh, bf16* __restrict__ yl,
    float* __restrict__ entp)
{
    __shared__ bf16 Qs[64][72];
    __shared__ bf16 Ks[64][72];
    __shared__ bf16 Vt[64][72];
    __shared__ float Hrow[64];

    const int tid = threadIdx.x, warp = tid >> 5, lane = tid & 31;
    const int g = lane >> 2, tg = lane & 3;
    const int qt = blockIdx.x, h = blockIdx.y, b = blockIdx.z;
    const int qm = warp * 16;
    const size_t base = (size_t)b * TT * (3 * CC) + (size_t)h * HD;

    #pragma unroll
    for (int it = 0; it < 8; ++it){
        const int i = tid + it * 128;
        const int r = i >> 4, c4 = (i & 15) * 4;
        float4 v = *(const float4*)(qkv + base + (size_t)(qt * 64 + r) * (3 * CC) + c4);
        bf16* d = &Qs[r][c4];
        d[0] = __float2bfloat16(v.x * 0.125f); d[1] = __float2bfloat16(v.y * 0.125f);
        d[2] = __float2bfloat16(v.z * 0.125f); d[3] = __float2bfloat16(v.w * 0.125f);
    }
    __syncthreads();
    uint32_t qa[4][4];
    #pragma unroll
    for (int kd = 0; kd < 4; kd++){
        const int k0 = kd * 16;
        qa[kd][0] = *(const uint32_t*)&Qs[qm + g    ][k0 + tg * 2];
        qa[kd][1] = *(const uint32_t*)&Qs[qm + g + 8][k0 + tg * 2];
        qa[kd][2] = *(const uint32_t*)&Qs[qm + g    ][k0 + tg * 2 + 8];
        qa[kd][3] = *(const uint32_t*)&Qs[qm + g + 8][k0 + tg * 2 + 8];
    }

    float mrow[2] = {-1e30f, -1e30f}, lrow[2] = {0.f, 0.f}, trow[2] = {0.f, 0.f};
    float o[8][4];
    #pragma unroll
    for (int nd = 0; nd < 8; nd++){ o[nd][0]=0.f; o[nd][1]=0.f; o[nd][2]=0.f; o[nd][3]=0.f; }

    for (int kt = 0; kt <= qt; ++kt){
        __syncthreads();
        #pragma unroll
        for (int it = 0; it < 8; ++it){
            const int i = tid + it * 128;
            const int r = i >> 4, c4 = (i & 15) * 4;
            const size_t rowoff = base + (size_t)(kt * 64 + r) * (3 * CC) + c4;
            float4 kv = *(const float4*)(qkv + rowoff + CC);
            bf16* d = &Ks[r][c4];
            d[0] = __float2bfloat16(kv.x); d[1] = __float2bfloat16(kv.y);
            d[2] = __float2bfloat16(kv.z); d[3] = __float2bfloat16(kv.w);
            float4 vv = *(const float4*)(qkv + rowoff + 2 * CC);
            Vt[c4    ][r] = __float2bfloat16(vv.x);
            Vt[c4 + 1][r] = __float2bfloat16(vv.y);
            Vt[c4 + 2][r] = __float2bfloat16(vv.z);
            Vt[c4 + 3][r] = __float2bfloat16(vv.w);
        }
        __syncthreads();

        float s[8][4];
        #pragma unroll
        for (int nt = 0; nt < 8; nt++){ s[nt][0]=0.f; s[nt][1]=0.f; s[nt][2]=0.f; s[nt][3]=0.f; }
        #pragma unroll
        for (int kd = 0; kd < 4; kd++){
            const int k0 = kd * 16;
            #pragma unroll
            for (int nt = 0; nt < 8; nt++){
                uint32_t b0 = *(const uint32_t*)&Ks[nt * 8 + g][k0 + tg * 2];
                uint32_t b1 = *(const uint32_t*)&Ks[nt * 8 + g][k0 + tg * 2 + 8];
                mma_bf16(s[nt], qa[kd][0], qa[kd][1], qa[kd][2], qa[kd][3], b0, b1);
            }
        }
        if (kt == qt){
            #pragma unroll
            for (int nt = 0; nt < 8; nt++){
                const int kc = nt * 8 + tg * 2;
                if (kc     > qm + g    ) s[nt][0] = -1e30f;
                if (kc + 1 > qm + g    ) s[nt][1] = -1e30f;
                if (kc     > qm + 8 + g) s[nt][2] = -1e30f;
                if (kc + 1 > qm + 8 + g) s[nt][3] = -1e30f;
            }
        }
        float tm0 = -1e30f, tm1 = -1e30f;
        #pragma unroll
        for (int nt = 0; nt < 8; nt++){
            tm0 = fmaxf(tm0, fmaxf(s[nt][0], s[nt][1]));
            tm1 = fmaxf(tm1, fmaxf(s[nt][2], s[nt][3]));
        }
        #pragma unroll
        for (int o2 = 1; o2 <= 2; o2 <<= 1){
            tm0 = fmaxf(tm0, __shfl_xor_sync(0xffffffffu, tm0, o2));
            tm1 = fmaxf(tm1, __shfl_xor_sync(0xffffffffu, tm1, o2));
        }
        const float m0n = fmaxf(mrow[0], tm0), m1n = fmaxf(mrow[1], tm1);
        const float c0 = __expf(mrow[0] - m0n), c1 = __expf(mrow[1] - m1n);
        float sp0 = 0.f, st0 = 0.f, sp1 = 0.f, st1 = 0.f;
        uint32_t pa[8], pb[8];
        #pragma unroll
        for (int nt = 0; nt < 8; nt++){
            float p0 = __expf(s[nt][0] - m0n), p1 = __expf(s[nt][1] - m0n);
            float p2 = __expf(s[nt][2] - m1n), p3 = __expf(s[nt][3] - m1n);
            sp0 += p0 + p1;  st0 += p0 * s[nt][0] + p1 * s[nt][1];
            sp1 += p2 + p3;  st1 += p2 * s[nt][2] + p3 * s[nt][3];
            pa[nt] = pack_bf16(p0, p1);
            pb[nt] = pack_bf16(p2, p3);
        }
        #pragma unroll
        for (int o2 = 1; o2 <= 2; o2 <<= 1){
            sp0 += __shfl_xor_sync(0xffffffffu, sp0, o2);
            st0 += __shfl_xor_sync(0xffffffffu, st0, o2);
            sp1 += __shfl_xor_sync(0xffffffffu, sp1, o2);
            st1 += __shfl_xor_sync(0xffffffffu, st1, o2);
        }
        lrow[0] = lrow[0] * c0 + sp0;  trow[0] = trow[0] * c0 + st0;  mrow[0] = m0n;
        lrow[1] = lrow[1] * c1 + sp1;  trow[1] = trow[1] * c1 + st1;  mrow[1] = m1n;
        #pragma unroll
        for (int nd = 0; nd < 8; nd++){
            o[nd][0] *= c0; o[nd][1] *= c0; o[nd][2] *= c1; o[nd][3] *= c1;
        }
        #pragma unroll
        for (int kc = 0; kc < 4; kc++){
            const uint32_t a0 = pa[2*kc], a1 = pb[2*kc], a2 = pa[2*kc+1], a3 = pb[2*kc+1];
            const int k0 = kc * 16;
            #pragma unroll
            for (int nd = 0; nd < 8; nd++){
                uint32_t b0 = *(const uint32_t*)&Vt[nd * 8 + g][k0 + tg * 2];
                uint32_t b1 = *(const uint32_t*)&Vt[nd * 8 + g][k0 + tg * 2 + 8];
                mma_bf16(o[nd], a0, a1, a2, a3, b0, b1);
            }
        }
    }

    const float il0 = 1.0f / lrow[0], il1 = 1.0f / lrow[1];
    const int q0 = qt * 64 + qm + g, q1 = q0 + 8;
    #pragma unroll
    for (int nd = 0; nd < 8; nd++){
        const int col = h * HD + nd * 8 + tg * 2;
        bf16 h0,l0,h1,l1;
        split2(o[nd][0] * il0, h0, l0); split2(o[nd][1] * il0, h1, l1);
        const size_t i0 = (size_t)(b * TT + q0) * CC + col;
        *(bf162*)(yh + i0) = bf162(h0, h1);
        *(bf162*)(yl + i0) = bf162(l0, l1);
        split2(o[nd][2] * il1, h0, l0); split2(o[nd][3] * il1, h1, l1);
        const size_t i1 = (size_t)(b * TT + q1) * CC + col;
        *(bf162*)(yh + i1) = bf162(h0, h1);
        *(bf162*)(yl + i1) = bf162(l0, l1);
    }
    const float H0 = mrow[0] + logf(lrow[0]) - trow[0] * il0;
    const float H1 = mrow[1] + logf(lrow[1]) - trow[1] * il1;
    if (tg == 0){ Hrow[qm + g] = H0; Hrow[qm + 8 + g] = H1; }
    __syncthreads();
    if (tid == 0){
        float ssum = 0.f;
        #pragma unroll
        for (int i = 0; i < 64; i++) ssum += Hrow[i];
        entp[(b * HH + h) * 32 + qt] = ssum;
    }
}

// ---------------- entropy final reduce -------------------------------------
__global__ __launch_bounds__(256) void entropy_reduce(const float* __restrict__ entp,
                                                      float* __restrict__ out)
{
    __shared__ float sh[8];
    const int tid = threadIdx.x;
    float s = entp[tid] + entp[tid + 256] + entp[tid + 512] + entp[tid + 768];
    #pragma unroll
    for (int o = 16; o; o >>= 1) s += __shfl_xor_sync(0xffffffffu, s, o);
    if ((tid & 31) == 0) sh[tid >> 5] = s;
    __syncthreads();
    if (tid == 0){
        float t = 0.f;
        #pragma unroll
        for (int i = 0; i < 8; i++) t += sh[i];
        out[0] = t * (1.0f / (float)(BB * HH * TT));
    }
}

// ---------------- launch ---------------------------------------------------
extern "C" void kernel_launch(void* const* d_in, const int* in_sizes, int n_in,
                              void* d_out, int out_size)
{
    (void)in_sizes; (void)n_in;
    const float* x      = (const float*)d_in[0];
    const float* ln1_w  = (const float*)d_in[1];
    const float* ln1_b  = (const float*)d_in[2];
    const float* attn_w = (const float*)d_in[3];
    const float* attn_b = (const float*)d_in[4];
    const float* ap_w   = (const float*)d_in[5];
    const float* ap_b   = (const float*)d_in[6];
    const float* ln2_w  = (const float*)d_in[7];
    const float* ln2_b  = (const float*)d_in[8];
    const float* fc_w   = (const float*)d_in[9];
    const float* fc_b   = (const float*)d_in[10];
    const float* pr_w   = (const float*)d_in[11];
    const float* pr_b   = (const float*)d_in[12];
    float* out = (float*)d_out;
    float* ent_out = out + (out_size - 1);

    bf16 *wq_h,*wq_l,*wap_h,*wap_l,*wfc_h,*wfc_l,*wpr_h,*wpr_l;
    bf16 *hln_h,*hln_l,*yatt_h,*yatt_l,*h2_h,*h2_l,*mact_h,*mact_l;
    float *qkv,*entp;
    cudaGetSymbolAddress((void**)&wq_h, g_wq_h);   cudaGetSymbolAddress((void**)&wq_l, g_wq_l);
    cudaGetSymbolAddress((void**)&wap_h, g_wap_h); cudaGetSymbolAddress((void**)&wap_l, g_wap_l);
    cudaGetSymbolAddress((void**)&wfc_h, g_wfc_h); cudaGetSymbolAddress((void**)&wfc_l, g_wfc_l);
    cudaGetSymbolAddress((void**)&wpr_h, g_wpr_h); cudaGetSymbolAddress((void**)&wpr_l, g_wpr_l);
    cudaGetSymbolAddress((void**)&hln_h, g_hln_h); cudaGetSymbolAddress((void**)&hln_l, g_hln_l);
    cudaGetSymbolAddress((void**)&yatt_h, g_yatt_h); cudaGetSymbolAddress((void**)&yatt_l, g_yatt_l);
    cudaGetSymbolAddress((void**)&h2_h, g_h2_h);   cudaGetSymbolAddress((void**)&h2_l, g_h2_l);
    cudaGetSymbolAddress((void**)&mact_h, g_mact_h); cudaGetSymbolAddress((void**)&mact_l, g_mact_l);
    cudaGetSymbolAddress((void**)&qkv, g_qkv);
    cudaGetSymbolAddress((void**)&entp, g_entp);

    cudaFuncSetAttribute(gemm_mma<EPI_QKV>,  cudaFuncAttributeMaxDynamicSharedMemorySize, GEMM_SMEM);
    cudaFuncSetAttribute(gemm_mma<EPI_RES>,  cudaFuncAttributeMaxDynamicSharedMemorySize, GEMM_SMEM);
    cudaFuncSetAttribute(gemm_mma<EPI_GELU>, cudaFuncAttributeMaxDynamicSharedMemorySize, GEMM_SMEM);

    // 1) weights -> hi/lo bf16 split
    split_copy<<<2048, 256>>>(attn_w, wq_h,  wq_l,  3*CC*CC/4);
    split_copy<<<1024, 256>>>(ap_w,   wap_h, wap_l, CC*CC/4);
    split_copy<<<2048, 256>>>(fc_w,   wfc_h, wfc_l, 4*CC*CC/4);
    split_copy<<<2048, 256>>>(pr_w,   wpr_h, wpr_l, CC*4*CC/4);
    // 2) LN1
    ln_kernel<<<MTOT, 256>>>(x, ln1_w, ln1_b, hln_h, hln_l);
    // 3) qkv = ln1 @ attn_w^T + attn_b        [4096 x 3072 x 1024]
    gemm_mma<EPI_QKV><<<dim3(3*CC/128, MTOT/128), 256, GEMM_SMEM>>>(
        hln_h, hln_l, wq_h, wq_l, attn_b, nullptr, qkv, nullptr, nullptr, 3*CC, CC);
    // 4) flash attention + entropy partials
    flash_kernel<<<dim3(TT/64, HH, BB), 128>>>(qkv, yatt_h, yatt_l, entp);
    // 5) entropy scalar
    entropy_reduce<<<1, 256>>>(entp, ent_out);
    // 6) x1 = x + yatt @ ap_w^T + ap_b        [4096 x 1024 x 1024]
    gemm_mma<EPI_RES><<<dim3(CC/128, MTOT/128), 256, GEMM_SMEM>>>(
        yatt_h, yatt_l, wap_h, wap_l, ap_b, x, out, nullptr, nullptr, CC, CC);
    // 7) LN2
    ln_kernel<<<MTOT, 256>>>(out, ln2_w, ln2_b, h2_h, h2_l);
    // 8) m = gelu(h2 @ fc_w^T + fc_b)         [4096 x 4096 x 1024]
    gemm_mma<EPI_GELU><<<dim3(4*CC/128, MTOT/128), 256, GEMM_SMEM>>>(
        h2_h, h2_l, wfc_h, wfc_l, fc_b, nullptr, nullptr, mact_h, mact_l, 4*CC, CC);
    // 9) x2 = x1 + m @ pr_w^T + pr_b          [4096 x 1024 x 4096]
    gemm_mma<EPI_RES><<<dim3(CC/128, MTOT/128), 256, GEMM_SMEM>>>(
        mact_h, mact_l, wpr_h, wpr_l, pr_b, out, out, nullptr, nullptr, CC, 4*CC);
}

// round 14
// speedup vs baseline: 1.9127x; 1.9127x over previous
#include <cuda_runtime.h>
#include <cuda_fp16.h>
#include <cuda_bf16.h>
#include <cstdint>
#include <cstddef>

#define BB 2
#define TT 2048
#define CC 1024
#define HH 16
#define HD 64
#define MTOT (BB*TT)
#define DINLINE __device__ __forceinline__
typedef __nv_bfloat16 bf16;
typedef __nv_bfloat162 bf162;

// ---------------- scratch ---------------------------------------------------
__device__ __half g_hln [MTOT*CC];
__device__ float  g_qkv [MTOT*3*CC];
__device__ __half g_yatt[MTOT*CC];
__device__ __half g_h2  [MTOT*CC];
__device__ __half g_mact[(size_t)MTOT*4*CC];
__device__ __half g_wq [3*CC*CC];
__device__ __half g_wap[CC*CC];
__device__ __half g_wfc[4*CC*CC];
__device__ __half g_wpr[CC*4*CC];
__device__ float  g_entp[1024];

// ---------------- helpers ---------------------------------------------------
DINLINE uint32_t smem_u32(const void* p){ return (uint32_t)__cvta_generic_to_shared(p); }
DINLINE void cp16(uint32_t s, const void* g){
    asm volatile("cp.async.cg.shared.global [%0], [%1], 16;\n" :: "r"(s), "l"(g));
}
DINLINE void cp_commit(){ asm volatile("cp.async.commit_group;\n"); }

DINLINE uint32_t pack_bf16(float lo, float hi){
    bf162 t = __floats2bfloat162_rn(lo, hi);
    return *reinterpret_cast<uint32_t*>(&t);
}
DINLINE void mma_f16(float* d, uint32_t a0,uint32_t a1,uint32_t a2,uint32_t a3,
                     uint32_t b0, uint32_t b1){
    asm volatile("mma.sync.aligned.m16n8k16.row.col.f32.f16.f16.f32 "
        "{%0,%1,%2,%3},{%4,%5,%6,%7},{%8,%9},{%0,%1,%2,%3};\n"
        : "+f"(d[0]),"+f"(d[1]),"+f"(d[2]),"+f"(d[3])
        : "r"(a0),"r"(a1),"r"(a2),"r"(a3),"r"(b0),"r"(b1));
}
DINLINE void mma_bf16(float* d, uint32_t a0,uint32_t a1,uint32_t a2,uint32_t a3,
                      uint32_t b0, uint32_t b1){
    asm volatile("mma.sync.aligned.m16n8k16.row.col.f32.bf16.bf16.f32 "
        "{%0,%1,%2,%3},{%4,%5,%6,%7},{%8,%9},{%0,%1,%2,%3};\n"
        : "+f"(d[0]),"+f"(d[1]),"+f"(d[2]),"+f"(d[3])
        : "r"(a0),"r"(a1),"r"(a2),"r"(a3),"r"(b0),"r"(b1));
}
DINLINE void ldsm4(uint32_t* r, uint32_t addr){
    asm volatile("ldmatrix.sync.aligned.m8n8.x4.shared.b16 {%0,%1,%2,%3}, [%4];"
        : "=r"(r[0]), "=r"(r[1]), "=r"(r[2]), "=r"(r[3]) : "r"(addr));
}
DINLINE float gelu_tanh(float v){
    float u = 0.7978845608028654f * (v + 0.044715f * v * v * v);
    return 0.5f * v * (1.0f + tanhf(u));
}

// ---------------- weight prep: fp32 -> fp16 ---------------------------------
__global__ void cvt_copy(const float* __restrict__ in, __half* __restrict__ out, int n4){
    int i = blockIdx.x * blockDim.x + threadIdx.x;
    int stride = gridDim.x * blockDim.x;
    for (; i < n4; i += stride){
        float4 v = ((const float4*)in)[i];
        ((__half2*)out)[i*2  ] = __floats2half2_rn(v.x, v.y);
        ((__half2*)out)[i*2+1] = __floats2half2_rn(v.z, v.w);
    }
}

// ---------------- LayerNorm -> fp16 -----------------------------------------
__global__ __launch_bounds__(256) void ln_kernel(
    const float* __restrict__ x, const float* __restrict__ w,
    const float* __restrict__ b, __half* __restrict__ oh)
{
    __shared__ float sS[8], sQ[8];
    __shared__ float sMean, sRstd;
    const int row = blockIdx.x, tid = threadIdx.x;
    float4 xv = *(const float4*)(x + (size_t)row * CC + tid * 4);
    float s = xv.x + xv.y + xv.z + xv.w;
    float q = xv.x*xv.x + xv.y*xv.y + xv.z*xv.z + xv.w*xv.w;
    #pragma unroll
    for (int o = 16; o; o >>= 1){
        s += __shfl_xor_sync(0xffffffffu, s, o);
        q += __shfl_xor_sync(0xffffffffu, q, o);
    }
    if ((tid & 31) == 0){ sS[tid >> 5] = s; sQ[tid >> 5] = q; }
    __syncthreads();
    if (tid == 0){
        float S = 0.f, Q = 0.f;
        #pragma unroll
        for (int i = 0; i < 8; i++){ S += sS[i]; Q += sQ[i]; }
        float mean = S * (1.0f / CC);
        sMean = mean; sRstd = rsqrtf(Q * (1.0f / CC) - mean * mean + 1e-5f);
    }
    __syncthreads();
    const float mean = sMean, r = sRstd;
    float4 wv = *(const float4*)(w + tid * 4);
    float4 bv = *(const float4*)(b + tid * 4);
    float v0 = (xv.x - mean) * r * wv.x + bv.x;
    float v1 = (xv.y - mean) * r * wv.y + bv.y;
    float v2 = (xv.z - mean) * r * wv.z + bv.z;
    float v3 = (xv.w - mean) * r * wv.w + bv.w;
    size_t o4 = (size_t)row * (CC/2) + tid * 2;
    ((__half2*)oh)[o4  ] = __floats2half2_rn(v0, v1);
    ((__half2*)oh)[o4+1] = __floats2half2_rn(v2, v3);
}

// ---------------- fp16 single-pass GEMM (mma.sync + ldmatrix) --------------
// out[M,N] = epi( A[M,K] @ B[N,K]^T + bias[N] )
// 128x128 tile, BK=32, 8 warps (2m x 4n), double-buffered cp.async, 2 CTA/SM.
#define EPI_QKV  0
#define EPI_RES  1
#define EPI_GELU 2
#define ROWB   80u              // 32 fp16 data + 8 pad = 80 bytes/row
#define MATB   10240u           // 128 rows * 80B
#define STGB   20480u           // A | B
#define GEMM_SMEM (2*STGB)      // 40960

template<int EPI>
__global__ __launch_bounds__(256, 2) void gemm_mma(
    const __half* __restrict__ A, const __half* __restrict__ B,
    const float* __restrict__ bias, const float* __restrict__ res,
    float* __restrict__ outf, __half* __restrict__ outh,
    int N, int K)
{
    extern __shared__ char dsm[];
    const uint32_t sb = smem_u32(dsm);
    const int tid = threadIdx.x, warp = tid >> 5, lane = tid & 31;
    const int bm = blockIdx.y * 128, bn = blockIdx.x * 128;
    const int wm = (warp >> 2) * 64, wn = (warp & 3) * 32;

    // cp.async: thread -> row (tid>>1), two 16B chunks of A and of B
    const int lrow = tid >> 1, lc = (tid & 1) * 2;
    const __half* gA = A + (size_t)(bm + lrow) * K;
    const __half* gB = B + (size_t)(bn + lrow) * K;
    const uint32_t srow = (uint32_t)lrow * ROWB;

    // ldmatrix lane constants
    const int lr8 = (((lane >> 3) & 1) << 3) + (lane & 7);
    const int lk8 = (lane >> 4) << 3;
    const int g = lane >> 2, tg = lane & 3;

    float acc[4][4][4];
    #pragma unroll
    for (int mi = 0; mi < 4; mi++)
        #pragma unroll
        for (int nf = 0; nf < 4; nf++){
            acc[mi][nf][0]=0.f; acc[mi][nf][1]=0.f; acc[mi][nf][2]=0.f; acc[mi][nf][3]=0.f;
        }

    const int KT = K >> 5;

    #define LOADST(J) do{ \
        const uint32_t _b = sb + (uint32_t)((J) & 1) * STGB; \
        const int _ko = (J) << 5; \
        _Pragma("unroll") \
        for (int c = 0; c < 2; c++){ \
            const uint32_t so = srow + (uint32_t)(lc + c) * 16u; \
            const int go = _ko + (lc + c) * 8; \
            cp16(_b        + so, gA + go); \
            cp16(_b + MATB + so, gB + go); \
        } \
        cp_commit(); \
    } while(0)

    LOADST(0);

    for (int kt = 0; kt < KT; ++kt){
        if (kt + 1 < KT){
            LOADST(kt + 1);
            asm volatile("cp.async.wait_group 1;\n");
        } else {
            asm volatile("cp.async.wait_group 0;\n");
        }
        __syncthreads();
        const uint32_t base = sb + (uint32_t)(kt & 1) * STGB;
        #pragma unroll
        for (int ks = 0; ks < 2; ++ks){
            const uint32_t kb = (uint32_t)((ks * 16 + lk8) * 2);
            uint32_t a[4][4];
            #pragma unroll
            for (int mi = 0; mi < 4; mi++)
                ldsm4(a[mi], base + (uint32_t)(wm + mi*16 + lr8) * ROWB + kb);
            uint32_t bfr[2][4];
            #pragma unroll
            for (int ng = 0; ng < 2; ng++)
                ldsm4(bfr[ng], base + MATB + (uint32_t)(wn + ng*16 + lr8) * ROWB + kb);
            #pragma unroll
            for (int mi = 0; mi < 4; mi++){
                #pragma unroll
                for (int nf = 0; nf < 4; nf++){
                    const int ng = nf >> 1, h = nf & 1;
                    mma_f16(acc[mi][nf], a[mi][0],a[mi][1],a[mi][2],a[mi][3],
                            bfr[ng][h], bfr[ng][2 + h]);
                }
            }
        }
        __syncthreads();
    }

    // epilogue
    #pragma unroll
    for (int mi = 0; mi < 4; mi++){
        const int m0 = bm + wm + mi * 16 + g;
        #pragma unroll
        for (int nf = 0; nf < 4; nf++){
            const int col = bn + wn + nf * 8 + tg * 2;
            const float bv0 = bias[col], bv1 = bias[col + 1];
            float v00 = acc[mi][nf][0] + bv0, v01 = acc[mi][nf][1] + bv1;
            float v10 = acc[mi][nf][2] + bv0, v11 = acc[mi][nf][3] + bv1;
            const size_t i0 = (size_t)m0 * N + col;
            const size_t i1 = (size_t)(m0 + 8) * N + col;
            if (EPI == EPI_RES){
                float2 r0v = *(const float2*)(res + i0);
                float2 r1v = *(const float2*)(res + i1);
                v00 += r0v.x; v01 += r0v.y; v10 += r1v.x; v11 += r1v.y;
                *(float2*)(outf + i0) = make_float2(v00, v01);
                *(float2*)(outf + i1) = make_float2(v10, v11);
            } else if (EPI == EPI_GELU){
                *(__half2*)(outh + i0) = __floats2half2_rn(gelu_tanh(v00), gelu_tanh(v01));
                *(__half2*)(outh + i1) = __floats2half2_rn(gelu_tanh(v10), gelu_tanh(v11));
            } else {
                *(float2*)(outf + i0) = make_float2(v00, v01);
                *(float2*)(outf + i1) = make_float2(v10, v11);
            }
        }
    }
    #undef LOADST
}

// ---------------- flash attention + streaming entropy ----------------------
__global__ __launch_bounds__(128) void flash_kernel(
    const float* __restrict__ qkv, __half* __restrict__ y, float* __restrict__ entp)
{
    __shared__ bf16 Qs[64][72];
    __shared__ bf16 Ks[64][72];
    __shared__ bf16 Vt[64][72];
    __shared__ float Hrow[64];

    const int tid = threadIdx.x, warp = tid >> 5, lane = tid & 31;
    const int g = lane >> 2, tg = lane & 3;
    const int qt = blockIdx.x, h = blockIdx.y, b = blockIdx.z;
    const int qm = warp * 16;
    const size_t base = (size_t)b * TT * (3 * CC) + (size_t)h * HD;

    #pragma unroll
    for (int it = 0; it < 8; ++it){
        const int i = tid + it * 128;
        const int r = i >> 4, c4 = (i & 15) * 4;
        float4 v = *(const float4*)(qkv + base + (size_t)(qt * 64 + r) * (3 * CC) + c4);
        bf16* d = &Qs[r][c4];
        d[0] = __float2bfloat16(v.x * 0.125f); d[1] = __float2bfloat16(v.y * 0.125f);
        d[2] = __float2bfloat16(v.z * 0.125f); d[3] = __float2bfloat16(v.w * 0.125f);
    }
    __syncthreads();
    uint32_t qa[4][4];
    #pragma unroll
    for (int kd = 0; kd < 4; kd++){
        const int k0 = kd * 16;
        qa[kd][0] = *(const uint32_t*)&Qs[qm + g    ][k0 + tg * 2];
        qa[kd][1] = *(const uint32_t*)&Qs[qm + g + 8][k0 + tg * 2];
        qa[kd][2] = *(const uint32_t*)&Qs[qm + g    ][k0 + tg * 2 + 8];
        qa[kd][3] = *(const uint32_t*)&Qs[qm + g + 8][k0 + tg * 2 + 8];
    }

    float mrow[2] = {-1e30f, -1e30f}, lrow[2] = {0.f, 0.f}, trow[2] = {0.f, 0.f};
    float o[8][4];
    #pragma unroll
    for (int nd = 0; nd < 8; nd++){ o[nd][0]=0.f; o[nd][1]=0.f; o[nd][2]=0.f; o[nd][3]=0.f; }

    for (int kt = 0; kt <= qt; ++kt){
        __syncthreads();
        #pragma unroll
        for (int it = 0; it < 8; ++it){
            const int i = tid + it * 128;
            const int r = i >> 4, c4 = (i & 15) * 4;
            const size_t rowoff = base + (size_t)(kt * 64 + r) * (3 * CC) + c4;
            float4 kv = *(const float4*)(qkv + rowoff + CC);
            bf16* d = &Ks[r][c4];
            d[0] = __float2bfloat16(kv.x); d[1] = __float2bfloat16(kv.y);
            d[2] = __float2bfloat16(kv.z); d[3] = __float2bfloat16(kv.w);
            float4 vv = *(const float4*)(qkv + rowoff + 2 * CC);
            Vt[c4    ][r] = __float2bfloat16(vv.x);
            Vt[c4 + 1][r] = __float2bfloat16(vv.y);
            Vt[c4 + 2][r] = __float2bfloat16(vv.z);
            Vt[c4 + 3][r] = __float2bfloat16(vv.w);
        }
        __syncthreads();

        float s[8][4];
        #pragma unroll
        for (int nt = 0; nt < 8; nt++){ s[nt][0]=0.f; s[nt][1]=0.f; s[nt][2]=0.f; s[nt][3]=0.f; }
        #pragma unroll
        for (int kd = 0; kd < 4; kd++){
            const int k0 = kd * 16;
            #pragma unroll
            for (int nt = 0; nt < 8; nt++){
                uint32_t b0 = *(const uint32_t*)&Ks[nt * 8 + g][k0 + tg * 2];
                uint32_t b1 = *(const uint32_t*)&Ks[nt * 8 + g][k0 + tg * 2 + 8];
                mma_bf16(s[nt], qa[kd][0], qa[kd][1], qa[kd][2], qa[kd][3], b0, b1);
            }
        }
        if (kt == qt){
            #pragma unroll
            for (int nt = 0; nt < 8; nt++){
                const int kc = nt * 8 + tg * 2;
                if (kc     > qm + g    ) s[nt][0] = -1e30f;
                if (kc + 1 > qm + g    ) s[nt][1] = -1e30f;
                if (kc     > qm + 8 + g) s[nt][2] = -1e30f;
                if (kc + 1 > qm + 8 + g) s[nt][3] = -1e30f;
            }
        }
        float tm0 = -1e30f, tm1 = -1e30f;
        #pragma unroll
        for (int nt = 0; nt < 8; nt++){
            tm0 = fmaxf(tm0, fmaxf(s[nt][0], s[nt][1]));
            tm1 = fmaxf(tm1, fmaxf(s[nt][2], s[nt][3]));
        }
        #pragma unroll
        for (int o2 = 1; o2 <= 2; o2 <<= 1){
            tm0 = fmaxf(tm0, __shfl_xor_sync(0xffffffffu, tm0, o2));
            tm1 = fmaxf(tm1, __shfl_xor_sync(0xffffffffu, tm1, o2));
        }
        const float m0n = fmaxf(mrow[0], tm0), m1n = fmaxf(mrow[1], tm1);
        const float c0 = __expf(mrow[0] - m0n), c1 = __expf(mrow[1] - m1n);
        float sp0 = 0.f, st0 = 0.f, sp1 = 0.f, st1 = 0.f;
        uint32_t pa[8], pb[8];
        #pragma unroll
        for (int nt = 0; nt < 8; nt++){
            float p0 = __expf(s[nt][0] - m0n), p1 = __expf(s[nt][1] - m0n);
            float p2 = __expf(s[nt][2] - m1n), p3 = __expf(s[nt][3] - m1n);
            sp0 += p0 + p1;  st0 += p0 * s[nt][0] + p1 * s[nt][1];
            sp1 += p2 + p3;  st1 += p2 * s[nt][2] + p3 * s[nt][3];
            pa[nt] = pack_bf16(p0, p1);
            pb[nt] = pack_bf16(p2, p3);
        }
        #pragma unroll
        for (int o2 = 1; o2 <= 2; o2 <<= 1){
            sp0 += __shfl_xor_sync(0xffffffffu, sp0, o2);
            st0 += __shfl_xor_sync(0xffffffffu, st0, o2);
            sp1 += __shfl_xor_sync(0xffffffffu, sp1, o2);
            st1 += __shfl_xor_sync(0xffffffffu, st1, o2);
        }
        lrow[0] = lrow[0] * c0 + sp0;  trow[0] = trow[0] * c0 + st0;  mrow[0] = m0n;
        lrow[1] = lrow[1] * c1 + sp1;  trow[1] = trow[1] * c1 + st1;  mrow[1] = m1n;
        #pragma unroll
        for (int nd = 0; nd < 8; nd++){
            o[nd][0] *= c0; o[nd][1] *= c0; o[nd][2] *= c1; o[nd][3] *= c1;
        }
        #pragma unroll
        for (int kc = 0; kc < 4; kc++){
            const uint32_t a0 = pa[2*kc], a1 = pb[2*kc], a2 = pa[2*kc+1], a3 = pb[2*kc+1];
            const int k0 = kc * 16;
            #pragma unroll
            for (int nd = 0; nd < 8; nd++){
                uint32_t b0 = *(const uint32_t*)&Vt[nd * 8 + g][k0 + tg * 2];
                uint32_t b1 = *(const uint32_t*)&Vt[nd * 8 + g][k0 + tg * 2 + 8];
                mma_bf16(o[nd], a0, a1, a2, a3, b0, b1);
            }
        }
    }

    const float il0 = 1.0f / lrow[0], il1 = 1.0f / lrow[1];
    const int q0 = qt * 64 + qm + g, q1 = q0 + 8;
    #pragma unroll
    for (int nd = 0; nd < 8; nd++){
        const int col = h * HD + nd * 8 + tg * 2;
        const size_t i0 = (size_t)(b * TT + q0) * CC + col;
        const size_t i1 = (size_t)(b * TT + q1) * CC + col;
        *(__half2*)(y + i0) = __floats2half2_rn(o[nd][0] * il0, o[nd][1] * il0);
        *(__half2*)(y + i1) = __floats2half2_rn(o[nd][2] * il1, o[nd][3] * il1);
    }
    const float H0 = mrow[0] + logf(lrow[0]) - trow[0] * il0;
    const float H1 = mrow[1] + logf(lrow[1]) - trow[1] * il1;
    if (tg == 0){ Hrow[qm + g] = H0; Hrow[qm + 8 + g] = H1; }
    __syncthreads();
    if (tid == 0){
        float ssum = 0.f;
        #pragma unroll
        for (int i = 0; i < 64; i++) ssum += Hrow[i];
        entp[(b * HH + h) * 32 + qt] = ssum;
    }
}

// ---------------- entropy final reduce -------------------------------------
__global__ __launch_bounds__(256) void entropy_reduce(const float* __restrict__ entp,
                                                      float* __restrict__ out)
{
    __shared__ float sh[8];
    const int tid = threadIdx.x;
    float s = entp[tid] + entp[tid + 256] + entp[tid + 512] + entp[tid + 768];
    #pragma unroll
    for (int o = 16; o; o >>= 1) s += __shfl_xor_sync(0xffffffffu, s, o);
    if ((tid & 31) == 0) sh[tid >> 5] = s;
    __syncthreads();
    if (tid == 0){
        float t = 0.f;
        #pragma unroll
        for (int i = 0; i < 8; i++) t += sh[i];
        out[0] = t * (1.0f / (float)(BB * HH * TT));
    }
}

// ---------------- launch ---------------------------------------------------
extern "C" void kernel_launch(void* const* d_in, const int* in_sizes, int n_in,
                              void* d_out, int out_size)
{
    (void)in_sizes; (void)n_in;
    const float* x      = (const float*)d_in[0];
    const float* ln1_w  = (const float*)d_in[1];
    const float* ln1_b  = (const float*)d_in[2];
    const float* attn_w = (const float*)d_in[3];
    const float* attn_b = (const float*)d_in[4];
    const float* ap_w   = (const float*)d_in[5];
    const float* ap_b   = (const float*)d_in[6];
    const float* ln2_w  = (const float*)d_in[7];
    const float* ln2_b  = (const float*)d_in[8];
    const float* fc_w   = (const float*)d_in[9];
    const float* fc_b   = (const float*)d_in[10];
    const float* pr_w   = (const float*)d_in[11];
    const float* pr_b   = (const float*)d_in[12];
    float* out = (float*)d_out;
    float* ent_out = out + (out_size - 1);

    __half *wq,*wap,*wfc,*wpr,*hln,*yatt,*h2,*mact;
    float *qkv,*entp;
    cudaGetSymbolAddress((void**)&wq,  g_wq);
    cudaGetSymbolAddress((void**)&wap, g_wap);
    cudaGetSymbolAddress((void**)&wfc, g_wfc);
    cudaGetSymbolAddress((void**)&wpr, g_wpr);
    cudaGetSymbolAddress((void**)&hln, g_hln);
    cudaGetSymbolAddress((void**)&yatt, g_yatt);
    cudaGetSymbolAddress((void**)&h2,  g_h2);
    cudaGetSymbolAddress((void**)&mact, g_mact);
    cudaGetSymbolAddress((void**)&qkv, g_qkv);
    cudaGetSymbolAddress((void**)&entp, g_entp);

    cudaFuncSetAttribute(gemm_mma<EPI_QKV>,  cudaFuncAttributeMaxDynamicSharedMemorySize, GEMM_SMEM);
    cudaFuncSetAttribute(gemm_mma<EPI_RES>,  cudaFuncAttributeMaxDynamicSharedMemorySize, GEMM_SMEM);
    cudaFuncSetAttribute(gemm_mma<EPI_GELU>, cudaFuncAttributeMaxDynamicSharedMemorySize, GEMM_SMEM);

    // 1) weights -> fp16
    cvt_copy<<<2048, 256>>>(attn_w, wq,  3*CC*CC/4);
    cvt_copy<<<1024, 256>>>(ap_w,   wap, CC*CC/4);
    cvt_copy<<<2048, 256>>>(fc_w,   wfc, 4*CC*CC/4);
    cvt_copy<<<2048, 256>>>(pr_w,   wpr, CC*4*CC/4);
    // 2) LN1
    ln_kernel<<<MTOT, 256>>>(x, ln1_w, ln1_b, hln);
    // 3) qkv = ln1 @ attn_w^T + attn_b        [4096 x 3072 x 1024]
    gemm_mma<EPI_QKV><<<dim3(3*CC/128, MTOT/128), 256, GEMM_SMEM>>>(
        hln, wq, attn_b, nullptr, qkv, nullptr, 3*CC, CC);
    // 4) flash attention + entropy partials
    flash_kernel<<<dim3(TT/64, HH, BB), 128>>>(qkv, yatt, entp);
    // 5) entropy scalar
    entropy_reduce<<<1, 256>>>(entp, ent_out);
    // 6) x1 = x + yatt @ ap_w^T + ap_b        [4096 x 1024 x 1024]
    gemm_mma<EPI_RES><<<dim3(CC/128, MTOT/128), 256, GEMM_SMEM>>>(
        yatt, wap, ap_b, x, out, nullptr, CC, CC);
    // 7) LN2
    ln_kernel<<<MTOT, 256>>>(out, ln2_w, ln2_b, h2);
    // 8) m = gelu(h2 @ fc_w^T + fc_b)         [4096 x 4096 x 1024]
    gemm_mma<EPI_GELU><<<dim3(4*CC/128, MTOT/128), 256, GEMM_SMEM>>>(
        h2, wfc, fc_b, nullptr, nullptr, mact, 4*CC, CC);
    // 9) x2 = x1 + m @ pr_w^T + pr_b          [4096 x 1024 x 4096]
    gemm_mma<EPI_RES><<<dim3(CC/128, MTOT/128), 256, GEMM_SMEM>>>(
        mact, wpr, pr_b, out, out, nullptr, CC, 4*CC);
}